// round 13
// baseline (speedup 1.0000x reference)
#include <cuda_runtime.h>
#include <math.h>

#define BB 16
#define FF 2048
#define SS 512
#define DD 256
#define DH 512
#define NSEG (BB*SS)      // 8192
#define NEDGE (BB*FF)     // 32768
#define DLAT 512
#define NB 148
#define NT 1024           // 32 warps/SM

typedef unsigned long long ull;

// ---- scratch ----
__device__ __align__(16) float g_P[2*SS*DH];
__device__ __align__(16) float g_Eb[8*DH];
__device__ __align__(16) float g_Rc[8*DH];
__device__ __align__(16) float g_H[NSEG*DH];
__device__ float g_pooled[BB*DD];
__device__ __align__(16) int g_cnt[NSEG];
__device__ int   g_off[NSEG];
__device__ int   g_run[NSEG];
__device__ unsigned g_perm[2*NEDGE];
__device__ unsigned g_arrive_ctr = 0;
__device__ unsigned g_release_ctr = 0;

__device__ __forceinline__ float gelu_f(float x){
    return 0.5f*x*(1.0f + erff(x*0.70710678118654752440f));
}
__device__ __forceinline__ ull addf2(ull a, ull b){
    ull r; asm("add.rn.f32x2 %0, %1, %2;" : "=l"(r) : "l"(a), "l"(b)); return r;
}
__device__ __forceinline__ ull mulf2(ull a, ull b){
    ull r; asm("mul.rn.f32x2 %0, %1, %2;" : "=l"(r) : "l"(a), "l"(b)); return r;
}
__device__ __forceinline__ ull fmaf2_(ull a, ull b, ull c){
    ull r; asm("fma.rn.f32x2 %0, %1, %2, %3;" : "=l"(r) : "l"(a), "l"(b), "l"(c)); return r;
}
__device__ __forceinline__ void ffma2(ull &d, ull a, ull b){
    asm("fma.rn.f32x2 %0, %1, %2, %0;" : "+l"(d) : "l"(a), "l"(b));
}
__device__ __forceinline__ ull pack2(float x){
    ull r; asm("mov.b64 %0, {%1, %1};" : "=l"(r) : "f"(x)); return r;
}
__device__ __forceinline__ void unpack2(float &lo, float &hi, ull v){
    asm("mov.b64 {%0, %1}, %2;" : "=f"(lo), "=f"(hi) : "l"(v));
}

// ---- software grid barrier ----
__device__ __forceinline__ void gsync(){
    __threadfence();
    __syncthreads();
    if (threadIdx.x == 0){
        unsigned t = atomicAdd(&g_arrive_ctr, 1u) + 1u;
        if ((t % NB) == 0u){
            atomicAdd(&g_release_ctr, 1u);
        } else {
            unsigned target = (t + NB - 1u) / NB;
            volatile unsigned* rel = &g_release_ctr;
            while (*rel < target) { __nanosleep(32); }
        }
    }
    __syncthreads();
    __threadfence();
}

#define SMRF 10752   // floats (43 KB)

__global__ __launch_bounds__(NT, 1)
void k_fused(const int* __restrict__ a0, const int* __restrict__ a1,
             const int* __restrict__ pidx, const int* __restrict__ ridx,
             const float* __restrict__ pos, const float* __restrict__ pre,
             const float* __restrict__ rol,
             const float* __restrict__ W1, const float* __restrict__ b1,
             const float* __restrict__ W2, const float* __restrict__ b2,
             const float* __restrict__ lng, const float* __restrict__ lnb,
             const float* __restrict__ Wl1, const float* __restrict__ bl1,
             const float* __restrict__ Wl2, const float* __restrict__ bl2,
             float* __restrict__ out){
    __shared__ __align__(16) float smr_f[SMRF];
    int blk = blockIdx.x, tid = threadIdx.x;
    int gid = blk*NT + tid;

    // ---------- A: zero ----------
    if (gid < NSEG)  g_cnt[gid] = 0;
    if (gid < BB*DD) g_pooled[gid] = 0.f;
    gsync();

    // ---------- B: count ----------
    if (gid < NEDGE){
        int e = gid;
        int b = e >> 11;
        int v0 = a0[e], v1 = a1[e], p = pidx[e];
        bool role = (p == 1);
        int dstf = role ? v0 : v1;
        atomicAdd(&g_cnt[b*SS + dstf], 1);
        if (!role && p != 0) atomicAdd(&g_cnt[b*SS + v0], 1);
    }
    gsync();

    // ---------- C: scan (blk 0) || precompute tables (blks 1..144) ----------
    if (blk == 0){
        int base = tid*8;
        int s = 0;
        #pragma unroll
        for (int i=0;i<8;i++) s += g_cnt[base+i];
        int lane = tid&31, warp = tid>>5;
        int x = s;
        #pragma unroll
        for (int o=1;o<32;o<<=1){ int y=__shfl_up_sync(0xffffffffu,x,o); if(lane>=o) x+=y; }
        int* wsum = (int*)smr_f;
        if (lane==31) wsum[warp] = x;
        __syncthreads();
        int wb = 0;
        for (int w=0; w<warp; w++) wb += wsum[w];
        int run = x - s + wb;
        #pragma unroll
        for (int i=0;i<8;i++){
            g_off[base+i] = run; g_run[base+i] = run;
            run += g_cnt[base+i];
        }
    } else if (blk <= 128){
        // pos tile 64x64 with 1024 threads: each thread 1 row x 4 cols
        int w = blk - 1;
        int nx = w&7, my = (w>>3)&7, z = w>>6;
        const float* Bm = W1 + (z ? (size_t)2*DD*DH : 0);
        float* C = g_P + (size_t)z * SS*DH;
        float (*As)[68] = (float(*)[68])smr_f;
        float (*Bs)[64] = (float(*)[64])(smr_f + 16*68);
        int bm = my*64, bn = nx*64;
        int ty = tid >> 4, tx = tid & 15;     // ty 0..63 row, tx 0..15 col4
        float acc[4] = {0.f,0.f,0.f,0.f};
        for (int k0=0;k0<DD;k0+=16){
            {
                int m_ = tid>>4, kl = tid&15;
                As[kl][m_] = pos[(size_t)(bm+m_)*DD + k0 + kl];
                int kb = tid>>6, nn = tid&63;
                Bs[kb][nn] = Bm[(size_t)(k0+kb)*DH + bn + nn];
            }
            __syncthreads();
            #pragma unroll
            for (int k=0;k<16;k++){
                float av = As[k][ty];
                #pragma unroll
                for (int j=0;j<4;j++) acc[j] += av*Bs[k][tx*4+j];
            }
            __syncthreads();
        }
        #pragma unroll
        for (int j=0;j<4;j++)
            C[(size_t)(bm+ty)*DH + bn+tx*4+j] = acc[j];
    } else if (blk <= 144){
        int r8 = blk - 129;
        const float* A; const float* W; float* C; int r;
        if (r8 < 8){ A=pre; W=W1+DD*DH;   C=g_Eb; r=r8; }
        else       { A=rol; W=W1+2*DD*DH; C=g_Rc; r=r8-8; }
        float* a = (float*)smr_f;
        if (tid < DD) a[tid] = A[r*DD + tid];
        __syncthreads();
        if (tid < DH){
            float s = 0.f;
            #pragma unroll 4
            for (int k=0;k<DD;k++) s += a[k]*W[(size_t)k*DH + tid];
            C[r*DH + tid] = s;
        }
    }
    gsync();

    // ---------- D: place ----------
    if (gid < NEDGE){
        int e = gid;
        int b = e >> 11;
        int v0=a0[e], v1=a1[e], p=pidx[e];
        bool role = (p==1);
        unsigned descf; int dstf;
        if (role){ dstf=v0; descf=(unsigned)v0 | ((unsigned)(ridx[e]+1)<<10) | ((unsigned)p<<20) | (1u<<23); }
        else     { dstf=v1; descf=(unsigned)v0 | ((unsigned)v1<<10)          | ((unsigned)p<<20); }
        int slot = atomicAdd(&g_run[b*SS+dstf],1);
        g_perm[slot]=descf;
        if (!role && p!=0){
            unsigned descb = (unsigned)v1 | ((unsigned)v0<<10) | ((unsigned)p<<20);
            slot = atomicAdd(&g_run[b*SS+v0],1);
            g_perm[slot]=descb;
        }
    }
    gsync();

    // ---------- E: gather, 16 nodes/block-iter, 64 thr/node ----------
    {
        int sub = tid >> 6;                   // 0..15
        int wg  = tid & 63;
        int c0i = wg*2, c1i = wg*2+1;
        const ulonglong2* PA = reinterpret_cast<const ulonglong2*>(g_P);
        const ulonglong2* PC = PA + (size_t)SS*DH/4;
        const ulonglong2* EBt = reinterpret_cast<const ulonglong2*>(g_Eb);
        const ulonglong2* RCt = reinterpret_cast<const ulonglong2*>(g_Rc);
        ulonglong2 bA = reinterpret_cast<const ulonglong2*>(b1)[c0i];
        ulonglong2 bB = reinterpret_cast<const ulonglong2*>(b1)[c1i];
        const ull kC6 = pack2(-2.9761905e-3f);
        const ull kC4 = pack2( 2.5e-2f);
        const ull kC2 = pack2(-1.6666667e-1f);
        const ull kONE= pack2(1.0f);
        const ull kHA = pack2(0.3989422804f);
        const ull kHALF=pack2(0.5f);
        #define GELU1(u, acc) do{ \
            ull x2 = mulf2(u,u); \
            ull p_ = fmaf2_(x2, kC6, kC4); p_ = fmaf2_(x2, p_, kC2); p_ = fmaf2_(x2, p_, kONE); \
            acc = fmaf2_(mulf2(x2,p_), kHA, acc); acc = fmaf2_(u, kHALF, acc); \
        }while(0)

        for (int base = blk*16; base < NSEG; base += NB*16){
            int node = base + sub;
            int start = g_off[node];
            int cnt = g_cnt[node];
            ull ac0=0, ac1=0, ac2=0, ac3=0;
            for (int m=0; m<cnt; m++){
                unsigned d = g_perm[start+m];
                int iA = d & 1023, iC = (d>>10)&1023, p = (d>>20)&7;
                const ulonglong2* T = (d & (1u<<23)) ? RCt : PC;
                ulonglong2 av0 = PA[(size_t)iA*128 + c0i];
                ulonglong2 av1 = PA[(size_t)iA*128 + c1i];
                ulonglong2 cv0 = T[(size_t)iC*128 + c0i];
                ulonglong2 cv1 = T[(size_t)iC*128 + c1i];
                ulonglong2 ev0 = EBt[(size_t)p*128 + c0i];
                ulonglong2 ev1 = EBt[(size_t)p*128 + c1i];
                ull u0 = addf2(addf2(av0.x, cv0.x), addf2(ev0.x, bA.x));
                ull u1 = addf2(addf2(av0.y, cv0.y), addf2(ev0.y, bA.y));
                ull u2 = addf2(addf2(av1.x, cv1.x), addf2(ev1.x, bB.x));
                ull u3 = addf2(addf2(av1.y, cv1.y), addf2(ev1.y, bB.y));
                GELU1(u0, ac0); GELU1(u1, ac1); GELU1(u2, ac2); GELU1(u3, ac3);
            }
            ulonglong2 r0; r0.x = ac0; r0.y = ac1;
            ulonglong2 r1; r1.x = ac2; r1.y = ac3;
            reinterpret_cast<ulonglong2*>(g_H)[(size_t)node*128 + c0i] = r0;
            reinterpret_cast<ulonglong2*>(g_H)[(size_t)node*128 + c1i] = r1;
        }
        #undef GELU1
    }
    gsync();

    // ---------- F: 64x256 GEMM tile + fused LN + pooling (128 blocks, 1024 thr) ----------
    if (blk < 128){
        float* As_ = smr_f;                   // [2][16][68]
        float* Bs_ = smr_f + 2*16*68;         // [2][16][260]
        const float* A = g_H; const float* B = W2;
        const int K = DH;
        int bm = blk*64;
        int ty = tid >> 6, tx = tid & 63;     // ty 0..15 (4 rows), tx 0..63 (4 cols)

        int ar = tid >> 2, ac = tid & 3;      // A loader: tid<256
        int br = tid >> 6, bc = tid & 63;     // B loader: all 1024 -> 16x64 float4

        float4 pa = make_float4(0.f,0.f,0.f,0.f), pb;
        if (tid < 256)
            pa = *reinterpret_cast<const float4*>(&A[(size_t)(bm+ar)*K + ac*4]);
        pb = *reinterpret_cast<const float4*>(&B[(size_t)br*DD + bc*4]);

        ull acc2[2][4];
        #pragma unroll
        for (int i=0;i<2;i++)
            #pragma unroll
            for (int j=0;j<4;j++) acc2[i][j]=0ull;

        int buf = 0;
        if (tid < 256){
            As_[(ac*4+0)*68 + ar]=pa.x; As_[(ac*4+1)*68 + ar]=pa.y;
            As_[(ac*4+2)*68 + ar]=pa.z; As_[(ac*4+3)*68 + ar]=pa.w;
        }
        *reinterpret_cast<float4*>(&Bs_[br*260 + bc*4]) = pb;
        __syncthreads();

        const int ktiles = K/16;
        for (int kt=0; kt<ktiles; kt++){
            bool more = (kt+1 < ktiles);
            if (more){
                int kk = (kt+1)*16;
                if (tid < 256)
                    pa = *reinterpret_cast<const float4*>(&A[(size_t)(bm+ar)*K + kk + ac*4]);
                pb = *reinterpret_cast<const float4*>(&B[(size_t)(kk+br)*DD + bc*4]);
            }
            int bo = buf*1088, bo2 = buf*4160;
            #pragma unroll
            for (int k=0;k<16;k++){
                const ull* a64 = reinterpret_cast<const ull*>(&As_[bo + k*68 + ty*4]);
                ull ap0=a64[0], ap1=a64[1];
                float4 bf = *reinterpret_cast<const float4*>(&Bs_[bo2 + k*260 + tx*4]);
                float bv[4] = {bf.x,bf.y,bf.z,bf.w};
                #pragma unroll
                for (int j=0;j<4;j++){
                    ull bb = pack2(bv[j]);
                    ffma2(acc2[0][j], ap0, bb);
                    ffma2(acc2[1][j], ap1, bb);
                }
            }
            if (more){
                buf ^= 1;
                if (tid < 256){
                    As_[buf*1088 + (ac*4+0)*68 + ar]=pa.x; As_[buf*1088 + (ac*4+1)*68 + ar]=pa.y;
                    As_[buf*1088 + (ac*4+2)*68 + ar]=pa.z; As_[buf*1088 + (ac*4+3)*68 + ar]=pa.w;
                }
                *reinterpret_cast<float4*>(&Bs_[buf*4160 + br*260 + bc*4]) = pb;
                __syncthreads();
            }
        }

        // ---- fused epilogue ----
        float* st = smr_f;                    // 32x260 staging
        float* sp = smr_f + 8320;             // 256 pooled partials
        int warp = tid>>5, lane = tid&31;
        int bIdx = blk >> 3;
        int sBase = (blk & 7)*64;
        float accp[8];
        #pragma unroll
        for (int i=0;i<8;i++) accp[i]=0.f;

        __syncthreads();
        if (tid < DD) sp[tid] = 0.f;

        #pragma unroll
        for (int p=0; p<2; p++){
            __syncthreads();
            if ((ty>>3) == p){
                int rbase = (ty&7)*4;         // local rows rbase..rbase+3
                #pragma unroll
                for (int rp=0; rp<2; rp++){
                    float lo[4], hi[4];
                    #pragma unroll
                    for (int j=0;j<4;j++) unpack2(lo[j], hi[j], acc2[rp][j]);
                    *reinterpret_cast<float4*>(&st[(rbase+2*rp)*260 + tx*4])   = make_float4(lo[0],lo[1],lo[2],lo[3]);
                    *reinterpret_cast<float4*>(&st[(rbase+2*rp+1)*260 + tx*4]) = make_float4(hi[0],hi[1],hi[2],hi[3]);
                }
            }
            __syncthreads();
            {
                int local = warp;             // 32 warps -> 32 rows per pass
                int node = bm + p*32 + local;
                int spos = sBase + p*32 + local;
                float cntf = (float)g_cnt[node];
                float x[8]; float sum=0.f;
                #pragma unroll
                for (int i=0;i<8;i++){
                    int j = lane + 32*i;
                    x[i] = st[local*260 + j] + pos[(size_t)spos*DD + j] + cntf*b2[j];
                    sum += x[i];
                }
                #pragma unroll
                for (int o=16;o;o>>=1) sum += __shfl_xor_sync(0xffffffffu,sum,o);
                float mu = sum*(1.0f/DD);
                float vs=0.f;
                #pragma unroll
                for (int i=0;i<8;i++){ float d2 = x[i]-mu; vs += d2*d2; }
                #pragma unroll
                for (int o=16;o;o>>=1) vs += __shfl_xor_sync(0xffffffffu,vs,o);
                float inv = rsqrtf(vs*(1.0f/DD)+1e-5f);
                #pragma unroll
                for (int i=0;i<8;i++){
                    int j = lane+32*i;
                    accp[i] += (x[i]-mu)*inv*lng[j] + lnb[j];
                }
            }
        }
        __syncthreads();
        #pragma unroll
        for (int i=0;i<8;i++) atomicAdd(&sp[lane+32*i], accp[i]);
        __syncthreads();
        if (tid < DD) atomicAdd(&g_pooled[bIdx*DD+tid], sp[tid]);
    }
    gsync();

    // ---------- H: final MLP (16 blocks) ----------
    if (blk < BB){
        float* pp = smr_f;
        float* hh = pp + DD;
        if (tid < DD) pp[tid] = g_pooled[blk*DD+tid]*(1.0f/SS);
        __syncthreads();
        if (tid < DLAT){
            int j = tid;
            float s = bl1[j];
            #pragma unroll 4
            for (int k=0;k<DD;k++) s += pp[k]*Wl1[(size_t)k*DLAT+j];
            hh[j] = gelu_f(s);
        }
        __syncthreads();
        if (tid < DLAT){
            int j = tid;
            float o = bl2[j];
            #pragma unroll 4
            for (int k=0;k<DLAT;k++) o += hh[k]*Wl2[(size_t)k*DLAT+j];
            out[(size_t)blk*DLAT+j] = o;
        }
    }
}

extern "C" void kernel_launch(void* const* d_in, const int* in_sizes, int n_in,
                              void* d_out, int out_size){
    const int*   a0   = (const int*)d_in[0];
    const int*   a1   = (const int*)d_in[1];
    const int*   pidx = (const int*)d_in[2];
    const int*   ridx = (const int*)d_in[3];
    const float* pos  = (const float*)d_in[5];
    const float* pre  = (const float*)d_in[6];
    const float* rol  = (const float*)d_in[7];
    const float* W1   = (const float*)d_in[8];
    const float* b1   = (const float*)d_in[9];
    const float* W2   = (const float*)d_in[10];
    const float* b2   = (const float*)d_in[11];
    const float* lng  = (const float*)d_in[12];
    const float* lnb  = (const float*)d_in[13];
    const float* Wl1  = (const float*)d_in[14];
    const float* bl1  = (const float*)d_in[15];
    const float* Wl2  = (const float*)d_in[16];
    const float* bl2  = (const float*)d_in[17];
    float* out = (float*)d_out;

    k_fused<<<NB, NT>>>(a0, a1, pidx, ridx, pos, pre, rol,
                        W1, b1, W2, b2, lng, lnb, Wl1, bl1, Wl2, bl2, out);
}

// round 16
// speedup vs baseline: 1.2242x; 1.2242x over previous
#include <cuda_runtime.h>
#include <cstdint>
#include <stdint.h>
#include <math.h>

#define BB 16
#define FF 2048
#define SS 512
#define DD 256
#define DH 512
#define NSEG (BB*SS)      // 8192
#define NEDGE (BB*FF)     // 32768
#define DLAT 512
#define NB 148
#define NT 512

typedef unsigned long long ull;

// ---- scratch ----
__device__ __align__(16) float g_P[2*SS*DH];
__device__ __align__(16) float g_Eb[8*DH];
__device__ __align__(16) float g_Rc[8*DH];
__device__ float g_pooled[BB*DD];
__device__ __align__(16) int g_cnt[NSEG];
__device__ int   g_off[NSEG];
__device__ int   g_run[NSEG];
__device__ unsigned g_perm[2*NEDGE];
__device__ unsigned g_arrive_ctr = 0;
__device__ unsigned g_release_ctr = 0;

__device__ __forceinline__ float gelu_f(float x){
    return 0.5f*x*(1.0f + erff(x*0.70710678118654752440f));
}
__device__ __forceinline__ ull addf2(ull a, ull b){
    ull r; asm("add.rn.f32x2 %0, %1, %2;" : "=l"(r) : "l"(a), "l"(b)); return r;
}
__device__ __forceinline__ ull mulf2(ull a, ull b){
    ull r; asm("mul.rn.f32x2 %0, %1, %2;" : "=l"(r) : "l"(a), "l"(b)); return r;
}
__device__ __forceinline__ ull fmaf2_(ull a, ull b, ull c){
    ull r; asm("fma.rn.f32x2 %0, %1, %2, %3;" : "=l"(r) : "l"(a), "l"(b), "l"(c)); return r;
}
__device__ __forceinline__ void ffma2(ull &d, ull a, ull b){
    asm("fma.rn.f32x2 %0, %1, %2, %0;" : "+l"(d) : "l"(a), "l"(b));
}
__device__ __forceinline__ ull pack2(float x){
    ull r; asm("mov.b64 %0, {%1, %1};" : "=l"(r) : "f"(x)); return r;
}
__device__ __forceinline__ void unpack2(float &lo, float &hi, ull v){
    asm("mov.b64 {%0, %1}, %2;" : "=f"(lo), "=f"(hi) : "l"(v));
}

// ---- software grid barrier ----
__device__ __forceinline__ void gsync(){
    __threadfence();
    __syncthreads();
    if (threadIdx.x == 0){
        unsigned t = atomicAdd(&g_arrive_ctr, 1u) + 1u;
        if ((t % NB) == 0u){
            atomicAdd(&g_release_ctr, 1u);
        } else {
            unsigned target = (t + NB - 1u) / NB;
            volatile unsigned* rel = &g_release_ctr;
            while (*rel < target) { __nanosleep(64); }
        }
    }
    __syncthreads();
    __threadfence();
}

// smem layout (floats): Ht[64][516] at 0 (33024), Bs[2][16][260] at 33024 (8320),
// st reuses Bs, sp[256] at 41344. total 41600 floats = 166400 B.
#define HT_STRIDE 516
#define BS_OFF 33024
#define SP_OFF 41344
#define SMEMB 166400

__global__ __launch_bounds__(NT, 1)
void k_fused(const int* __restrict__ a0, const int* __restrict__ a1,
             const int* __restrict__ pidx, const int* __restrict__ ridx,
             const float* __restrict__ pos, const float* __restrict__ pre,
             const float* __restrict__ rol,
             const float* __restrict__ W1, const float* __restrict__ b1,
             const float* __restrict__ W2, const float* __restrict__ b2,
             const float* __restrict__ lng, const float* __restrict__ lnb,
             const float* __restrict__ Wl1, const float* __restrict__ bl1,
             const float* __restrict__ Wl2, const float* __restrict__ bl2,
             float* __restrict__ out){
    extern __shared__ __align__(16) float smr_f[];
    int blk = blockIdx.x, tid = threadIdx.x;
    int gid = blk*NT + tid;

    // ---------- A: zero ----------
    if (gid < NSEG)  g_cnt[gid] = 0;
    if (gid < BB*DD) g_pooled[gid] = 0.f;
    gsync();

    // ---------- B: count ----------
    if (gid < NEDGE){
        int e = gid;
        int b = e >> 11;
        int v0 = a0[e], v1 = a1[e], p = pidx[e];
        bool role = (p == 1);
        int dstf = role ? v0 : v1;
        atomicAdd(&g_cnt[b*SS + dstf], 1);
        if (!role && p != 0) atomicAdd(&g_cnt[b*SS + v0], 1);
    }
    gsync();

    // ---------- C: scan (blk0) || pos tables (1..128) || small tables (129..144) ----------
    if (blk == 0){
        int base = tid*16;
        int s = 0;
        #pragma unroll 4
        for (int i=0;i<16;i++) s += g_cnt[base+i];
        int lane = tid&31, warp = tid>>5;
        int x = s;
        #pragma unroll
        for (int o=1;o<32;o<<=1){ int y=__shfl_up_sync(0xffffffffu,x,o); if(lane>=o) x+=y; }
        int* wsum = (int*)smr_f;
        if (lane==31) wsum[warp] = x;
        __syncthreads();
        int wb = 0;
        for (int w=0; w<warp; w++) wb += wsum[w];
        int run = x - s + wb;
        #pragma unroll 4
        for (int i=0;i<16;i++){
            g_off[base+i] = run; g_run[base+i] = run;
            run += g_cnt[base+i];
        }
    } else if (blk <= 128){
        int w = blk - 1;
        int nx = w&7, my = (w>>3)&7, z = w>>6;
        const float* Bm = W1 + (z ? (size_t)2*DD*DH : 0);
        float* C = g_P + (size_t)z * SS*DH;
        float (*As)[68] = (float(*)[68])smr_f;
        float (*Bs)[64] = (float(*)[64])(smr_f + 16*68);
        int bm = my*64, bn = nx*64;
        int ty = tid >> 4, tx = tid & 15;
        float acc[2][4] = {};
        for (int k0=0;k0<DD;k0+=16){
            #pragma unroll
            for (int h=0; h<2; h++){
                int i = tid + h*NT;
                int m_ = i>>4, kl = i&15;
                As[kl][m_] = pos[(size_t)(bm+m_)*DD + k0 + kl];
                int kb = i>>6, nn = i&63;
                Bs[kb][nn] = Bm[(size_t)(k0+kb)*DH + bn + nn];
            }
            __syncthreads();
            #pragma unroll
            for (int k=0;k<16;k++){
                float av0 = As[k][ty*2], av1 = As[k][ty*2+1];
                float bv[4];
                #pragma unroll
                for (int j=0;j<4;j++) bv[j]=Bs[k][tx*4+j];
                #pragma unroll
                for (int j=0;j<4;j++){ acc[0][j] += av0*bv[j]; acc[1][j] += av1*bv[j]; }
            }
            __syncthreads();
        }
        #pragma unroll
        for (int i=0;i<2;i++)
            #pragma unroll
            for (int j=0;j<4;j++)
                C[(size_t)(bm+ty*2+i)*DH + bn+tx*4+j] = acc[i][j];
    } else if (blk <= 144){
        int r8 = blk - 129;
        const float* A; const float* W; float* C; int r;
        if (r8 < 8){ A=pre; W=W1+DD*DH;   C=g_Eb; r=r8; }
        else       { A=rol; W=W1+2*DD*DH; C=g_Rc; r=r8-8; }
        float* a = (float*)smr_f;
        if (tid < DD) a[tid] = A[r*DD + tid];
        __syncthreads();
        float s = 0.f;
        #pragma unroll 4
        for (int k=0;k<DD;k++) s += a[k]*W[(size_t)k*DH + tid];
        C[r*DH + tid] = s;
    }
    gsync();

    // ---------- D: place ----------
    if (gid < NEDGE){
        int e = gid;
        int b = e >> 11;
        int v0=a0[e], v1=a1[e], p=pidx[e];
        bool role = (p==1);
        unsigned descf; int dstf;
        if (role){ dstf=v0; descf=(unsigned)v0 | ((unsigned)(ridx[e]+1)<<10) | ((unsigned)p<<20) | (1u<<23); }
        else     { dstf=v1; descf=(unsigned)v0 | ((unsigned)v1<<10)          | ((unsigned)p<<20); }
        int slot = atomicAdd(&g_run[b*SS+dstf],1);
        g_perm[slot]=descf;
        if (!role && p!=0){
            unsigned descb = (unsigned)v1 | ((unsigned)v0<<10) | ((unsigned)p<<20);
            slot = atomicAdd(&g_run[b*SS+v0],1);
            g_perm[slot]=descb;
        }
    }
    gsync();

    // ---------- EFG fused: gather 64 nodes -> smem; GEMM @W2; LN+pool (128 blocks) ----------
    if (blk < 128){
        float* Ht  = smr_f;                      // [64][516]
        float* Bs_ = smr_f + BS_OFF;             // [2][16][260]
        float* sp  = smr_f + SP_OFF;             // [256]
        int bm_n = blk*64;

        // --- gather: 8 node-subgroups x 8 iters, 64 thr/node ---
        {
            int sub = tid >> 6;                  // 0..7
            int wg  = tid & 63;
            int c0i = wg*2, c1i = wg*2+1;
            const ulonglong2* PA = reinterpret_cast<const ulonglong2*>(g_P);
            const ulonglong2* PC = PA + (size_t)SS*DH/4;
            const ulonglong2* EBt = reinterpret_cast<const ulonglong2*>(g_Eb);
            const ulonglong2* RCt = reinterpret_cast<const ulonglong2*>(g_Rc);
            ulonglong2 bA = reinterpret_cast<const ulonglong2*>(b1)[c0i];
            ulonglong2 bB = reinterpret_cast<const ulonglong2*>(b1)[c1i];
            const ull kC6 = pack2(-2.9761905e-3f);
            const ull kC4 = pack2( 2.5e-2f);
            const ull kC2 = pack2(-1.6666667e-1f);
            const ull kONE= pack2(1.0f);
            const ull kHA = pack2(0.3989422804f);
            const ull kHALF=pack2(0.5f);
            #define GELU1(u, acc) do{ \
                ull x2 = mulf2(u,u); \
                ull p_ = fmaf2_(x2, kC6, kC4); p_ = fmaf2_(x2, p_, kC2); p_ = fmaf2_(x2, p_, kONE); \
                acc = fmaf2_(mulf2(x2,p_), kHA, acc); acc = fmaf2_(u, kHALF, acc); \
            }while(0)
            for (int it=0; it<8; it++){
                int r = it*8 + sub;
                int node = bm_n + r;
                int start = g_off[node];
                int cnt = g_cnt[node];
                ull ac0=0, ac1=0, ac2=0, ac3=0;
                for (int m=0; m<cnt; m++){
                    unsigned d = g_perm[start+m];
                    int iA = d & 1023, iC = (d>>10)&1023, p = (d>>20)&7;
                    const ulonglong2* T = (d & (1u<<23)) ? RCt : PC;
                    ulonglong2 av0 = PA[(size_t)iA*128 + c0i];
                    ulonglong2 av1 = PA[(size_t)iA*128 + c1i];
                    ulonglong2 cv0 = T[(size_t)iC*128 + c0i];
                    ulonglong2 cv1 = T[(size_t)iC*128 + c1i];
                    ulonglong2 ev0 = EBt[(size_t)p*128 + c0i];
                    ulonglong2 ev1 = EBt[(size_t)p*128 + c1i];
                    ull u0 = addf2(addf2(av0.x, cv0.x), addf2(ev0.x, bA.x));
                    ull u1 = addf2(addf2(av0.y, cv0.y), addf2(ev0.y, bA.y));
                    ull u2 = addf2(addf2(av1.x, cv1.x), addf2(ev1.x, bB.x));
                    ull u3 = addf2(addf2(av1.y, cv1.y), addf2(ev1.y, bB.y));
                    GELU1(u0, ac0); GELU1(u1, ac1); GELU1(u2, ac2); GELU1(u3, ac3);
                }
                float f0,f1,f2,f3,f4,f5,f6,f7;
                unpack2(f0,f1,ac0); unpack2(f2,f3,ac1);
                unpack2(f4,f5,ac2); unpack2(f6,f7,ac3);
                float* hr = &Ht[r*HT_STRIDE + 8*wg];
                *reinterpret_cast<float4*>(hr)     = make_float4(f0,f1,f2,f3);
                *reinterpret_cast<float4*>(hr + 4) = make_float4(f4,f5,f6,f7);
            }
            #undef GELU1
        }
        __syncthreads();

        // --- GEMM: C[64][256] = Ht @ W2, B streamed in 16x256 tiles ---
        int ty = tid >> 6, tx = tid & 63;        // rows ty*8.., cols tx*4..
        int bi0 = tid*2, bi1 = tid*2+1;
        int br0 = bi0>>6, bc0 = bi0&63;
        int br1 = bi1>>6, bc1 = bi1&63;

        float4 pb0 = *reinterpret_cast<const float4*>(&W2[(size_t)br0*DD + bc0*4]);
        float4 pb1 = *reinterpret_cast<const float4*>(&W2[(size_t)br1*DD + bc1*4]);

        ull accC[8][2];
        #pragma unroll
        for (int i=0;i<8;i++){ accC[i][0]=0ull; accC[i][1]=0ull; }
        int rowb[8];
        #pragma unroll
        for (int i=0;i<8;i++) rowb[i] = (ty*8+i)*HT_STRIDE;

        int buf = 0;
        *reinterpret_cast<float4*>(&Bs_[br0*260 + bc0*4]) = pb0;
        *reinterpret_cast<float4*>(&Bs_[br1*260 + bc1*4]) = pb1;
        __syncthreads();

        for (int kt=0; kt<32; kt++){
            bool more = (kt+1 < 32);
            if (more){
                int kk2 = (kt+1)*16;
                pb0 = *reinterpret_cast<const float4*>(&W2[(size_t)(kk2+br0)*DD + bc0*4]);
                pb1 = *reinterpret_cast<const float4*>(&W2[(size_t)(kk2+br1)*DD + bc1*4]);
            }
            int bo = buf*4160;
            #pragma unroll
            for (int kk=0; kk<16; kk++){
                int k = kt*16 + kk;
                const ull* bp = reinterpret_cast<const ull*>(&Bs_[bo + kk*260 + tx*4]);
                ull bl0 = bp[0], bl1 = bp[1];
                #pragma unroll
                for (int i=0;i<8;i++){
                    ull ap = pack2(Ht[rowb[i] + k]);
                    ffma2(accC[i][0], ap, bl0);
                    ffma2(accC[i][1], ap, bl1);
                }
            }
            if (more){
                buf ^= 1;
                *reinterpret_cast<float4*>(&Bs_[buf*4160 + br0*260 + bc0*4]) = pb0;
                *reinterpret_cast<float4*>(&Bs_[buf*4160 + br1*260 + bc1*4]) = pb1;
                __syncthreads();
            }
        }

        // --- fused LN + pool epilogue (st reuses Bs region) ---
        float* st = Bs_;                          // [32][260]
        int warp = tid>>5, lane = tid&31;
        int bIdx = blk >> 3;
        int sBase = (blk & 7)*64;
        float accp[8];
        #pragma unroll
        for (int i=0;i<8;i++) accp[i]=0.f;

        __syncthreads();
        if (tid < DD) sp[tid] = 0.f;

        #pragma unroll
        for (int p=0; p<2; p++){
            __syncthreads();
            if ((ty>>2) == p){
                int mb = (ty&3)*8;
                #pragma unroll
                for (int i=0;i<8;i++){
                    int ml = mb + i;
                    #pragma unroll
                    for (int j=0;j<2;j++){
                        float lo, hi;
                        unpack2(lo, hi, accC[i][j]);
                        *reinterpret_cast<float2*>(&st[ml*260 + tx*4 + j*2]) = make_float2(lo,hi);
                    }
                }
            }
            __syncthreads();
            #pragma unroll
            for (int rr=0; rr<2; rr++){
                int local = warp*2 + rr;
                int node = bm_n + p*32 + local;
                int spos = sBase + p*32 + local;
                float cntf = (float)g_cnt[node];
                float x[8]; float sum=0.f;
                #pragma unroll
                for (int i=0;i<8;i++){
                    int j = lane + 32*i;
                    x[i] = st[local*260 + j] + pos[(size_t)spos*DD + j] + cntf*b2[j];
                    sum += x[i];
                }
                #pragma unroll
                for (int o=16;o;o>>=1) sum += __shfl_xor_sync(0xffffffffu,sum,o);
                float mu = sum*(1.0f/DD);
                float vs=0.f;
                #pragma unroll
                for (int i=0;i<8;i++){ float d2 = x[i]-mu; vs += d2*d2; }
                #pragma unroll
                for (int o=16;o;o>>=1) vs += __shfl_xor_sync(0xffffffffu,vs,o);
                float inv = rsqrtf(vs*(1.0f/DD)+1e-5f);
                #pragma unroll
                for (int i=0;i<8;i++){
                    int j = lane+32*i;
                    accp[i] += (x[i]-mu)*inv*lng[j] + lnb[j];
                }
            }
        }
        __syncthreads();
        #pragma unroll
        for (int i=0;i<8;i++) atomicAdd(&sp[lane+32*i], accp[i]);
        __syncthreads();
        if (tid < DD) atomicAdd(&g_pooled[bIdx*DD+tid], sp[tid]);
    }
    gsync();

    // ---------- H: final MLP (16 blocks) ----------
    if (blk < BB){
        float* pp = smr_f;
        float* hh = pp + DD;
        if (tid < DD) pp[tid] = g_pooled[blk*DD+tid]*(1.0f/SS);
        __syncthreads();
        {
            int j = tid;
            float s = bl1[j];
            #pragma unroll 4
            for (int k=0;k<DD;k++) s += pp[k]*Wl1[(size_t)k*DLAT+j];
            hh[j] = gelu_f(s);
        }
        __syncthreads();
        {
            int j = tid;
            float o = bl2[j];
            #pragma unroll 4
            for (int k=0;k<DLAT;k++) o += hh[k]*Wl2[(size_t)k*DLAT+j];
            out[(size_t)blk*DLAT+j] = o;
        }
    }
}

extern "C" void kernel_launch(void* const* d_in, const int* in_sizes, int n_in,
                              void* d_out, int out_size){
    const int*   a0   = (const int*)d_in[0];
    const int*   a1   = (const int*)d_in[1];
    const int*   pidx = (const int*)d_in[2];
    const int*   ridx = (const int*)d_in[3];
    const float* pos  = (const float*)d_in[5];
    const float* pre  = (const float*)d_in[6];
    const float* rol  = (const float*)d_in[7];
    const float* W1   = (const float*)d_in[8];
    const float* b1   = (const float*)d_in[9];
    const float* W2   = (const float*)d_in[10];
    const float* b2   = (const float*)d_in[11];
    const float* lng  = (const float*)d_in[12];
    const float* lnb  = (const float*)d_in[13];
    const float* Wl1  = (const float*)d_in[14];
    const float* bl1  = (const float*)d_in[15];
    const float* Wl2  = (const float*)d_in[16];
    const float* bl2  = (const float*)d_in[17];
    float* out = (float*)d_out;

    cudaFuncSetAttribute(k_fused, cudaFuncAttributeMaxDynamicSharedMemorySize, SMEMB);
    k_fused<<<NB, NT, SMEMB>>>(a0, a1, pidx, ridx, pos, pre, rol,
                               W1, b1, W2, b2, lng, lnb, Wl1, bl1, Wl2, bl2, out);
}